// round 13
// baseline (speedup 1.0000x reference)
#include <cuda_runtime.h>
#include <cuda_fp16.h>
#include <cstdint>

#define B_   2
#define N_   2048
#define E_   1024
#define H_   16
#define HD_  64
#define M_   (B_*N_)        // 4096
#define QKVC (H_*3*HD_)     // 3072

typedef __half fp16;

// ---------------- scratch (static __device__, no allocs) ----------------
__device__ fp16 g_x16 [M_*E_];
__device__ fp16 g_wq16[H_*E_*192];
__device__ fp16 g_wo16[E_*E_];
__device__ fp16 g_q16 [B_*H_*N_*HD_];   // pre-scaled by 1/sqrt(HD)
__device__ fp16 g_k16 [B_*H_*N_*HD_];
__device__ fp16 g_v16 [B_*H_*N_*HD_];
__device__ fp16 g_sa16[M_*E_];

// ---------------- helpers ----------------
__device__ __forceinline__ uint32_t smem_u32(const void* p) {
    uint32_t a;
    asm("{ .reg .u64 t; cvta.to.shared.u64 t, %1; cvt.u32.u64 %0, t; }"
        : "=r"(a) : "l"(p));
    return a;
}
__device__ __forceinline__ void mma_f16(float c[4], const uint32_t a[4],
                                        uint32_t b0, uint32_t b1) {
    asm("mma.sync.aligned.m16n8k16.row.col.f32.f16.f16.f32 "
        "{%0,%1,%2,%3}, {%4,%5,%6,%7}, {%8,%9}, {%0,%1,%2,%3};"
        : "+f"(c[0]), "+f"(c[1]), "+f"(c[2]), "+f"(c[3])
        : "r"(a[0]), "r"(a[1]), "r"(a[2]), "r"(a[3]), "r"(b0), "r"(b1));
}
// fp16-accumulate variant (D/C are 2 regs of packed half2)
__device__ __forceinline__ void mma_f16h(uint32_t c[2], const uint32_t a[4],
                                         uint32_t b0, uint32_t b1) {
    asm("mma.sync.aligned.m16n8k16.row.col.f16.f16.f16.f16 "
        "{%0,%1}, {%2,%3,%4,%5}, {%6,%7}, {%0,%1};"
        : "+r"(c[0]), "+r"(c[1])
        : "r"(a[0]), "r"(a[1]), "r"(a[2]), "r"(a[3]), "r"(b0), "r"(b1));
}
__device__ __forceinline__ void ldm4(uint32_t r[4], uint32_t addr) {
    asm volatile("ldmatrix.sync.aligned.m8n8.x4.shared.b16 {%0,%1,%2,%3}, [%4];"
                 : "=r"(r[0]), "=r"(r[1]), "=r"(r[2]), "=r"(r[3]) : "r"(addr));
}
__device__ __forceinline__ void ldm4t(uint32_t r[4], uint32_t addr) {
    asm volatile("ldmatrix.sync.aligned.m8n8.x4.trans.shared.b16 {%0,%1,%2,%3}, [%4];"
                 : "=r"(r[0]), "=r"(r[1]), "=r"(r[2]), "=r"(r[3]) : "r"(addr));
}
__device__ __forceinline__ uint32_t pack_f16(float v0, float v1) {
    __half2 h = __floats2half2_rn(v0, v1);
    return *reinterpret_cast<uint32_t*>(&h);
}
#define CP16(d, s)  asm volatile("cp.async.cg.shared.global [%0], [%1], 16;" :: "r"(d), "l"(s))
#define CP_COMMIT() asm volatile("cp.async.commit_group;" ::: "memory")
#define CP_WAIT0()  asm volatile("cp.async.wait_group 0;" ::: "memory")

// ---------------- pre-pass: fp32 -> fp16 (all three tensors, one launch) ------
#define C1 ((M_*E_)/4)
#define C2 ((H_*E_*192)/4)
#define C3 ((E_*E_)/4)
__global__ void cvt_all(const float* __restrict__ x, const float* __restrict__ wq,
                        const float* __restrict__ wo)
{
    int i = blockIdx.x * blockDim.x + threadIdx.x;
    int stride = gridDim.x * blockDim.x;
    for (; i < C1 + C2 + C3; i += stride) {
        const float4* s; uint2* d; int j;
        if (i < C1)           { s = (const float4*)x;  d = (uint2*)g_x16;  j = i; }
        else if (i < C1 + C2) { s = (const float4*)wq; d = (uint2*)g_wq16; j = i - C1; }
        else                  { s = (const float4*)wo; d = (uint2*)g_wo16; j = i - C1 - C2; }
        float4 v = s[j];
        d[j] = make_uint2(pack_f16(v.x, v.y), pack_f16(v.z, v.w));
    }
}

// GEMM smem geometry (per buffer, double buffered), BK=64:
// A @0: 128 rows x pitch 144; B @18432: 64 k-rows x pitch 272
#define GBUF2 35840
#define GEMM_SMEM (2*GBUF2)

#define GEMM_CHUNK_COMPUTE(base)                                                     \
    _Pragma("unroll")                                                                \
    for (int kk = 0; kk < 4; kk++) {                                                 \
        uint32_t af[2][4];                                                           \
        _Pragma("unroll")                                                            \
        for (int t = 0; t < 2; t++)                                                  \
            ldm4(af[t], (base) + (wm * 32 + t * 16 + lrA) * 144 + (kk * 16 + lcA) * 2); \
        _Pragma("unroll")                                                            \
        for (int np = 0; np < 4; np++) {                                             \
            uint32_t bf[4];                                                          \
            ldm4t(bf, (base) + 18432u + (kk * 16 + lrA) * 272                        \
                       + (wn * 64 + np * 16 + lcA) * 2);                             \
            _Pragma("unroll")                                                        \
            for (int t = 0; t < 2; t++)                                              \
            _Pragma("unroll")                                                        \
            for (int j = 0; j < 2; j++)                                              \
                mma_f16(acc[t][np * 2 + j], af[t], bf[j * 2], bf[j * 2 + 1]);        \
        }                                                                            \
    }

// ---------------- kernel 1: QKV projection (fp16 HMMA, BK=64) ----------------
__global__ __launch_bounds__(256, 2) void qkv_mma(const float* __restrict__ bias)
{
    extern __shared__ __align__(16) uint8_t dsm[];
    const uint32_t sb = smem_u32(dsm);
    const int tid = threadIdx.x, lane = tid & 31, wid = tid >> 5;
    const int wm = wid >> 1, wn = wid & 1;
    const int m0 = blockIdx.y * 128, n0 = blockIdx.x * 128;
    const int g = lane >> 2, cq = (lane & 3) * 2;
    const int lrA = (lane & 7) + ((lane >> 3) & 1) * 8, lcA = ((lane >> 4) & 1) * 8;

    const fp16* srcA[4]; uint32_t dstA[4];
    const fp16* srcB[4]; uint32_t dstB[4];
#pragma unroll
    for (int t = 0; t < 4; t++) {
        int j = t * 256 + tid, row = j >> 3, sg = (j & 7) * 8;
        srcA[t] = g_x16 + (size_t)(m0 + row) * E_ + sg;
        dstA[t] = row * 144 + sg * 2;
    }
#pragma unroll
    for (int t = 0; t < 4; t++) {
        int j = t * 256 + tid, k = j >> 4, sg = (j & 15) * 8;
        int col = n0 + sg, hh = col / 192, ff = col - hh * 192;
        srcB[t] = g_wq16 + (size_t)(hh * E_ + k) * 192 + ff;
        dstB[t] = 18432u + k * 272 + sg * 2;
    }

    float acc[2][8][4];
#pragma unroll
    for (int t = 0; t < 2; t++)
#pragma unroll
        for (int nt = 0; nt < 8; nt++)
#pragma unroll
            for (int j = 0; j < 4; j++) acc[t][nt][j] = 0.f;

#pragma unroll
    for (int t = 0; t < 4; t++) CP16(sb + dstA[t], srcA[t]);
#pragma unroll
    for (int t = 0; t < 4; t++) CP16(sb + dstB[t], srcB[t]);
    CP_COMMIT();

    for (int kc = 0; kc < 16; kc++) {
        const uint32_t base = sb + (uint32_t)(kc & 1) * GBUF2;
        CP_WAIT0();
        __syncthreads();
        if (kc < 15) {
            const uint32_t nb = sb + (uint32_t)((kc + 1) & 1) * GBUF2;
#pragma unroll
            for (int t = 0; t < 4; t++) { srcA[t] += 64;       CP16(nb + dstA[t], srcA[t]); }
#pragma unroll
            for (int t = 0; t < 4; t++) { srcB[t] += 64 * 192; CP16(nb + dstB[t], srcB[t]); }
            CP_COMMIT();
        }
        GEMM_CHUNK_COMPUTE(base)
    }

    // epilogue: +bias, fp16 scatter into K/Q/V planes (split order K,Q,V);
    // Q pre-scaled by 1/sqrt(HD)=0.125.
#pragma unroll
    for (int t = 0; t < 2; t++)
#pragma unroll
        for (int nt = 0; nt < 8; nt++) {
            int col = n0 + wn * 64 + nt * 8 + cq;
            float b0v = bias[col], b1v = bias[col + 1];
            int hh = col / 192, ff = col - hh * 192;
            int sel = ff >> 6, ffl = ff & 63;
            fp16* ph = (sel == 0) ? g_k16 : (sel == 1) ? g_q16 : g_v16;
            float scale = (sel == 1) ? 0.125f : 1.0f;
#pragma unroll
            for (int rh = 0; rh < 2; rh++) {
                int m = m0 + wm * 32 + t * 16 + g + rh * 8;
                int bb = m >> 11, n = m & (N_ - 1);
                uint32_t hp = pack_f16((acc[t][nt][rh * 2] + b0v) * scale,
                                       (acc[t][nt][rh * 2 + 1] + b1v) * scale);
                size_t idx = ((size_t)(bb * H_ + hh) * N_ + n) * HD_ + ffl;
                *(uint32_t*)(ph + idx) = hp;
            }
        }
}

// ---------------- kernel 2: causal flash attention (fp16; S in f16-accum) -----
// KV buffer: K@0 (64 x pitch144 = 9216), V@9216. ABUF=18432, double buffered.
// Q @2*ABUF (128 x 144 = 18432). Total 55296.
#define ABUF16 18432
#define ATTN_SMEM (2*ABUF16 + 18432)
__global__ __launch_bounds__(256, 2) void attn_mma()
{
    extern __shared__ __align__(16) uint8_t dsm[];
    const uint32_t sb = smem_u32(dsm);
    const int tid = threadIdx.x, lane = tid & 31, w = tid >> 5;
    const int qt = (int)gridDim.x - 1 - (int)blockIdx.x;   // big tiles first
    const int bhd = blockIdx.y;
    const int g = lane >> 2, cq = (lane & 3) * 2;
    const int lrA = (lane & 7) + ((lane >> 3) & 1) * 8, lcA = ((lane >> 4) & 1) * 8;
    const int lrB = (lane & 7) + ((lane >> 4) & 1) * 8, lcB = ((lane >> 3) & 1) * 8;
    const uint32_t QB = sb + 2 * ABUF16;
    const float L2E = 1.4426950408889634f;
    const int ktmax = 2 * qt + 1;   // >= 1 always

    const fp16* srcKV[4]; uint32_t dstKV[4];
#pragma unroll
    for (int t = 0; t < 4; t++) {
        int j = (t & 1) * 256 + tid, row = j >> 3, sg = (j & 7) * 8;
        srcKV[t] = ((t < 2) ? g_k16 : g_v16) + (size_t)(bhd * N_ + row) * HD_ + sg;
        dstKV[t] = ((t < 2) ? 0u : 9216u) + row * 144 + sg * 2;
    }
#pragma unroll
    for (int t = 0; t < 4; t++) CP16(sb + dstKV[t], srcKV[t]);
    CP_COMMIT();

    // stage Q (128x64 fp16, pre-scaled) in smem; frags loaded on demand
#pragma unroll
    for (int t = 0; t < 4; t++) {
        int j = t * 256 + tid, row = j >> 3, sg = (j & 7) * 8;
        uint4 v = ((const uint4*)g_q16)[((size_t)(bhd * N_ + qt * 128 + row) * HD_ + sg) >> 3];
        *(uint4*)((size_t)dsm + (QB - sb) + row * 144 + sg * 2) = v;
    }

    float o[8][4];
#pragma unroll
    for (int nt = 0; nt < 8; nt++)
#pragma unroll
        for (int j = 0; j < 4; j++) o[nt][j] = 0.f;
    float mrow[2] = {-1e30f, -1e30f}, lrow[2] = {0.f, 0.f};
    const int qr0 = qt * 128 + w * 16 + g;
    const int wmaxk = qt * 128 + w * 16 + 15;

    for (int kt = 0; kt <= ktmax; kt++) {
        const uint32_t base = sb + (uint32_t)(kt & 1) * ABUF16;
        CP_WAIT0();
        __syncthreads();
        if (kt < ktmax) {
            const uint32_t nb = sb + (uint32_t)((kt + 1) & 1) * ABUF16;
#pragma unroll
            for (int t = 0; t < 4; t++) { srcKV[t] += 64 * HD_; CP16(nb + dstKV[t], srcKV[t]); }
            CP_COMMIT();
        }
        if (kt * 64 <= wmaxk) {
            const uint32_t KB = base, VB = base + 9216;
            // ---- S = Q K^T with fp16 accumulators ----
            uint32_t s16[8][2];
#pragma unroll
            for (int nt = 0; nt < 8; nt++) { s16[nt][0] = 0u; s16[nt][1] = 0u; }
#pragma unroll
            for (int kk = 0; kk < 4; kk++) {
                uint32_t qf[4];
                ldm4(qf, QB + (w * 16 + lrA) * 144 + (kk * 16 + lcA) * 2);
#pragma unroll
                for (int np = 0; np < 4; np++) {
                    uint32_t kf[4];
                    ldm4(kf, KB + (np * 16 + lrB) * 144 + (kk * 16 + lcB) * 2);
#pragma unroll
                    for (int j = 0; j < 2; j++)
                        mma_f16h(s16[np * 2 + j], qf, kf[j * 2], kf[j * 2 + 1]);
                }
            }
            // unpack to fp32: d0 packs rows g (cols cq,cq+1), d1 packs rows g+8
            float s_[8][4];
#pragma unroll
            for (int nt = 0; nt < 8; nt++) {
                float2 lo = __half22float2(*reinterpret_cast<__half2*>(&s16[nt][0]));
                float2 hi = __half22float2(*reinterpret_cast<__half2*>(&s16[nt][1]));
                s_[nt][0] = lo.x; s_[nt][1] = lo.y;
                s_[nt][2] = hi.x; s_[nt][3] = hi.y;
            }
            // causal mask (Q already scaled)
            const int kbase = kt * 64;
#pragma unroll
            for (int nt = 0; nt < 8; nt++)
#pragma unroll
                for (int j = 0; j < 4; j++) {
                    int colg = kbase + nt * 8 + cq + (j & 1);
                    int rowg = (j < 2) ? qr0 : qr0 + 8;
                    if (colg > rowg) s_[nt][j] = -1e30f;
                }
            // online softmax; P as fp16x2 via ex2.approx.f16x2 packed into s_
#pragma unroll
            for (int a = 0; a < 2; a++) {
                float tm = -1e30f;
#pragma unroll
                for (int nt = 0; nt < 8; nt++)
                    tm = fmaxf(tm, fmaxf(s_[nt][a * 2], s_[nt][a * 2 + 1]));
                tm = fmaxf(tm, __shfl_xor_sync(0xffffffffu, tm, 1));
                tm = fmaxf(tm, __shfl_xor_sync(0xffffffffu, tm, 2));
                float mn = fmaxf(mrow[a], tm);
                float alpha = __expf(mrow[a] - mn);
                float mnl = mn * L2E;
                float rs = 0.f;
#pragma unroll
                for (int nt = 0; nt < 8; nt++) {
                    float e0 = __fmaf_rn(s_[nt][a * 2],     L2E, -mnl);
                    float e1 = __fmaf_rn(s_[nt][a * 2 + 1], L2E, -mnl);
                    __half2 h = h2exp2(__floats2half2_rn(e0, e1));
                    float2 pf = __half22float2(h);
                    rs += pf.x + pf.y;
                    s_[nt][a * 2] = __uint_as_float(*reinterpret_cast<uint32_t*>(&h));
                }
                rs += __shfl_xor_sync(0xffffffffu, rs, 1);
                rs += __shfl_xor_sync(0xffffffffu, rs, 2);
                lrow[a] = lrow[a] * alpha + rs;
                mrow[a] = mn;
#pragma unroll
                for (int nt = 0; nt < 8; nt++) {
                    o[nt][a * 2]     *= alpha;
                    o[nt][a * 2 + 1] *= alpha;
                }
            }
            // ---- O += P V (fp32 accum); P a-frags already packed in s_ ----
#pragma unroll
            for (int kk = 0; kk < 4; kk++) {
                uint32_t pa[4];
                pa[0] = __float_as_uint(s_[2 * kk][0]);
                pa[1] = __float_as_uint(s_[2 * kk][2]);
                pa[2] = __float_as_uint(s_[2 * kk + 1][0]);
                pa[3] = __float_as_uint(s_[2 * kk + 1][2]);
#pragma unroll
                for (int np = 0; np < 4; np++) {
                    uint32_t vf[4];
                    ldm4t(vf, VB + (kk * 16 + lrA) * 144 + (np * 16 + lcA) * 2);
#pragma unroll
                    for (int j = 0; j < 2; j++)
                        mma_f16(o[np * 2 + j], pa, vf[j * 2], vf[j * 2 + 1]);
                }
            }
        }
    }

    // epilogue: O/l -> fp16 sa [B,N,E]
    const int bb = bhd >> 4, hh = bhd & 15;
    float inv[2] = {1.f / lrow[0], 1.f / lrow[1]};
#pragma unroll
    for (int nt = 0; nt < 8; nt++) {
        int d = hh * 64 + nt * 8 + cq;
#pragma unroll
        for (int a = 0; a < 2; a++) {
            int n = qt * 128 + w * 16 + g + a * 8;
            uint32_t hp = pack_f16(o[nt][a * 2] * inv[a], o[nt][a * 2 + 1] * inv[a]);
            *(uint32_t*)(g_sa16 + (size_t)(bb * N_ + n) * E_ + d) = hp;
        }
    }
}

// ---------------- kernel 3: output projection (fp16, BK=64, 2-stage) ----------
__global__ __launch_bounds__(256, 2) void out_mma(const float* __restrict__ bias,
                                                  float* __restrict__ out)
{
    extern __shared__ __align__(16) uint8_t dsm[];
    const uint32_t sb = smem_u32(dsm);
    const int tid = threadIdx.x, lane = tid & 31, wid = tid >> 5;
    const int wm = wid >> 1, wn = wid & 1;
    const int m0 = blockIdx.y * 128, n0 = blockIdx.x * 128;
    const int g = lane >> 2, cq = (lane & 3) * 2;
    const int lrA = (lane & 7) + ((lane >> 3) & 1) * 8, lcA = ((lane >> 4) & 1) * 8;

    const fp16* srcA[4]; uint32_t dstA[4];
    const fp16* srcB[4]; uint32_t dstB[4];
#pragma unroll
    for (int t = 0; t < 4; t++) {
        int j = t * 256 + tid, row = j >> 3, sg = (j & 7) * 8;
        srcA[t] = g_sa16 + (size_t)(m0 + row) * E_ + sg;
        dstA[t] = row * 144 + sg * 2;
    }
#pragma unroll
    for (int t = 0; t < 4; t++) {
        int j = t * 256 + tid, k = j >> 4, sg = (j & 15) * 8;
        srcB[t] = g_wo16 + (size_t)k * E_ + n0 + sg;
        dstB[t] = 18432u + k * 272 + sg * 2;
    }

    float acc[2][8][4];
#pragma unroll
    for (int t = 0; t < 2; t++)
#pragma unroll
        for (int nt = 0; nt < 8; nt++)
#pragma unroll
            for (int j = 0; j < 4; j++) acc[t][nt][j] = 0.f;

#pragma unroll
    for (int t = 0; t < 4; t++) CP16(sb + dstA[t], srcA[t]);
#pragma unroll
    for (int t = 0; t < 4; t++) CP16(sb + dstB[t], srcB[t]);
    CP_COMMIT();

    for (int kc = 0; kc < 16; kc++) {
        const uint32_t base = sb + (uint32_t)(kc & 1) * GBUF2;
        CP_WAIT0();
        __syncthreads();
        if (kc < 15) {
            const uint32_t nb = sb + (uint32_t)((kc + 1) & 1) * GBUF2;
#pragma unroll
            for (int t = 0; t < 4; t++) { srcA[t] += 64;      CP16(nb + dstA[t], srcA[t]); }
#pragma unroll
            for (int t = 0; t < 4; t++) { srcB[t] += 64 * E_; CP16(nb + dstB[t], srcB[t]); }
            CP_COMMIT();
        }
        GEMM_CHUNK_COMPUTE(base)
    }

#pragma unroll
    for (int t = 0; t < 2; t++)
#pragma unroll
        for (int nt = 0; nt < 8; nt++) {
            int col = n0 + wn * 64 + nt * 8 + cq;
            float b0v = bias[col], b1v = bias[col + 1];
#pragma unroll
            for (int rh = 0; rh < 2; rh++) {
                int m = m0 + wm * 32 + t * 16 + g + rh * 8;
                float2 v;
                v.x = acc[t][nt][rh * 2 + 0] + b0v;
                v.y = acc[t][nt][rh * 2 + 1] + b1v;
                *(float2*)(out + (size_t)m * E_ + col) = v;
            }
        }
}

// ---------------------------------------------------------------------------
extern "C" void kernel_launch(void* const* d_in, const int* in_sizes, int n_in,
                              void* d_out, int out_size)
{
    const float* x    = (const float*)d_in[0];   // [B,N,E]
    const float* Wqkv = (const float*)d_in[1];   // [H,E,192]
    const float* bqkv = (const float*)d_in[2];   // [H,192]
    const float* Wout = (const float*)d_in[3];   // [E,E]
    const float* bout = (const float*)d_in[4];   // [E]
    float* out = (float*)d_out;                  // [B,N,E]

    static int configured = 0;
    if (!configured) {
        cudaFuncSetAttribute(qkv_mma,  cudaFuncAttributeMaxDynamicSharedMemorySize, GEMM_SMEM);
        cudaFuncSetAttribute(out_mma,  cudaFuncAttributeMaxDynamicSharedMemorySize, GEMM_SMEM);
        cudaFuncSetAttribute(attn_mma, cudaFuncAttributeMaxDynamicSharedMemorySize, ATTN_SMEM);
        configured = 1;
    }

    cvt_all<<<2048, 256>>>(x, Wqkv, Wout);

    dim3 g1(QKVC / 128, M_ / 128);   // 24 x 32
    qkv_mma<<<g1, 256, GEMM_SMEM>>>(bqkv);

    dim3 g2(N_ / 128, B_ * H_);      // 16 x 32
    attn_mma<<<g2, 256, ATTN_SMEM>>>();

    dim3 g3(E_ / 128, M_ / 128);     // 8 x 32
    out_mma<<<g3, 256, GEMM_SMEM>>>(bout, out);
}

// round 14
// speedup vs baseline: 1.5501x; 1.5501x over previous
#include <cuda_runtime.h>
#include <cuda_fp16.h>
#include <cstdint>

#define B_   2
#define N_   2048
#define E_   1024
#define H_   16
#define HD_  64
#define M_   (B_*N_)        // 4096
#define QKVC (H_*3*HD_)     // 3072

typedef __half fp16;

// ---------------- scratch (static __device__, no allocs) ----------------
__device__ fp16 g_x16 [M_*E_];
__device__ fp16 g_wq16[H_*E_*192];
__device__ fp16 g_wo16[E_*E_];
__device__ fp16 g_q16 [B_*H_*N_*HD_];   // pre-scaled by 1/sqrt(HD)
__device__ fp16 g_k16 [B_*H_*N_*HD_];
__device__ fp16 g_v16 [B_*H_*N_*HD_];
__device__ fp16 g_sa16[M_*E_];

// ---------------- helpers ----------------
__device__ __forceinline__ uint32_t smem_u32(const void* p) {
    uint32_t a;
    asm("{ .reg .u64 t; cvta.to.shared.u64 t, %1; cvt.u32.u64 %0, t; }"
        : "=r"(a) : "l"(p));
    return a;
}
__device__ __forceinline__ void mma_f16(float c[4], const uint32_t a[4],
                                        uint32_t b0, uint32_t b1) {
    asm volatile(
        "mma.sync.aligned.m16n8k16.row.col.f32.f16.f16.f32 "
        "{%0,%1,%2,%3}, {%4,%5,%6,%7}, {%8,%9}, {%0,%1,%2,%3};"
        : "+f"(c[0]), "+f"(c[1]), "+f"(c[2]), "+f"(c[3])
        : "r"(a[0]), "r"(a[1]), "r"(a[2]), "r"(a[3]), "r"(b0), "r"(b1));
}
__device__ __forceinline__ void ldm4(uint32_t r[4], uint32_t addr) {
    asm volatile("ldmatrix.sync.aligned.m8n8.x4.shared.b16 {%0,%1,%2,%3}, [%4];"
                 : "=r"(r[0]), "=r"(r[1]), "=r"(r[2]), "=r"(r[3]) : "r"(addr));
}
__device__ __forceinline__ void ldm4t(uint32_t r[4], uint32_t addr) {
    asm volatile("ldmatrix.sync.aligned.m8n8.x4.trans.shared.b16 {%0,%1,%2,%3}, [%4];"
                 : "=r"(r[0]), "=r"(r[1]), "=r"(r[2]), "=r"(r[3]) : "r"(addr));
}
__device__ __forceinline__ uint32_t pack_f16(float v0, float v1) {
    __half2 h = __floats2half2_rn(v0, v1);
    return *reinterpret_cast<uint32_t*>(&h);
}
#define CP16(d, s)  asm volatile("cp.async.cg.shared.global [%0], [%1], 16;" :: "r"(d), "l"(s))
#define CP_COMMIT() asm volatile("cp.async.commit_group;" ::: "memory")
#define CP_WAIT0()  asm volatile("cp.async.wait_group 0;" ::: "memory")

// ---------------- pre-pass: fp32 -> fp16 (all three tensors, one launch) ------
#define C1 ((M_*E_)/4)
#define C2 ((H_*E_*192)/4)
#define C3 ((E_*E_)/4)
__global__ void cvt_all(const float* __restrict__ x, const float* __restrict__ wq,
                        const float* __restrict__ wo)
{
    int i = blockIdx.x * blockDim.x + threadIdx.x;
    int stride = gridDim.x * blockDim.x;
    for (; i < C1 + C2 + C3; i += stride) {
        const float4* s; uint2* d; int j;
        if (i < C1)           { s = (const float4*)x;  d = (uint2*)g_x16;  j = i; }
        else if (i < C1 + C2) { s = (const float4*)wq; d = (uint2*)g_wq16; j = i - C1; }
        else                  { s = (const float4*)wo; d = (uint2*)g_wo16; j = i - C1 - C2; }
        float4 v = s[j];
        d[j] = make_uint2(pack_f16(v.x, v.y), pack_f16(v.z, v.w));
    }
}

// GEMM smem geometry (per buffer, double buffered), BK=64:
// A @0: 128 rows x pitch 144; B @18432: 64 k-rows x pitch 272
#define GBUF2 35840
#define GEMM_SMEM (2*GBUF2)

// ---------------- kernel 1: QKV projection (fp16 HMMA, BK=64) ----------------
__global__ __launch_bounds__(256, 2) void qkv_mma(const float* __restrict__ bias)
{
    extern __shared__ __align__(16) uint8_t dsm[];
    const uint32_t sb = smem_u32(dsm);
    const int tid = threadIdx.x, lane = tid & 31, wid = tid >> 5;
    const int wm = wid >> 1, wn = wid & 1;
    const int m0 = blockIdx.y * 128, n0 = blockIdx.x * 128;
    const int g = lane >> 2, cq = (lane & 3) * 2;
    const int lrA = (lane & 7) + ((lane >> 3) & 1) * 8, lcA = ((lane >> 4) & 1) * 8;

    const fp16* srcA[4]; uint32_t dstA[4];
    const fp16* srcB[4]; uint32_t dstB[4];
#pragma unroll
    for (int t = 0; t < 4; t++) {
        int j = t * 256 + tid, row = j >> 3, sg = (j & 7) * 8;
        srcA[t] = g_x16 + (size_t)(m0 + row) * E_ + sg;
        dstA[t] = row * 144 + sg * 2;
    }
#pragma unroll
    for (int t = 0; t < 4; t++) {
        int j = t * 256 + tid, k = j >> 4, sg = (j & 15) * 8;
        int col = n0 + sg, hh = col / 192, ff = col - hh * 192;
        srcB[t] = g_wq16 + (size_t)(hh * E_ + k) * 192 + ff;
        dstB[t] = 18432u + k * 272 + sg * 2;
    }

    float acc[2][8][4];
#pragma unroll
    for (int t = 0; t < 2; t++)
#pragma unroll
        for (int nt = 0; nt < 8; nt++)
#pragma unroll
            for (int j = 0; j < 4; j++) acc[t][nt][j] = 0.f;

#pragma unroll
    for (int t = 0; t < 4; t++) CP16(sb + dstA[t], srcA[t]);
#pragma unroll
    for (int t = 0; t < 4; t++) CP16(sb + dstB[t], srcB[t]);
    CP_COMMIT();

    for (int kc = 0; kc < 16; kc++) {
        const uint32_t base = sb + (uint32_t)(kc & 1) * GBUF2;
        CP_WAIT0();
        __syncthreads();
        if (kc < 15) {
            const uint32_t nb = sb + (uint32_t)((kc + 1) & 1) * GBUF2;
#pragma unroll
            for (int t = 0; t < 4; t++) { srcA[t] += 64;       CP16(nb + dstA[t], srcA[t]); }
#pragma unroll
            for (int t = 0; t < 4; t++) { srcB[t] += 64 * 192; CP16(nb + dstB[t], srcB[t]); }
            CP_COMMIT();
        }
#pragma unroll
        for (int kk = 0; kk < 4; kk++) {
            uint32_t af[2][4];
#pragma unroll
            for (int t = 0; t < 2; t++)
                ldm4(af[t], base + (wm * 32 + t * 16 + lrA) * 144 + (kk * 16 + lcA) * 2);
#pragma unroll
            for (int np = 0; np < 4; np++) {
                uint32_t bf[4];
                ldm4t(bf, base + 18432u + (kk * 16 + lrA) * 272
                           + (wn * 64 + np * 16 + lcA) * 2);
#pragma unroll
                for (int t = 0; t < 2; t++)
#pragma unroll
                    for (int j = 0; j < 2; j++)
                        mma_f16(acc[t][np * 2 + j], af[t], bf[j * 2], bf[j * 2 + 1]);
            }
        }
    }

    // epilogue: +bias, fp16 scatter into K/Q/V planes (split order K,Q,V);
    // Q is pre-scaled by 1/sqrt(HD)=0.125 here so attn skips the scale.
#pragma unroll
    for (int t = 0; t < 2; t++)
#pragma unroll
        for (int nt = 0; nt < 8; nt++) {
            int col = n0 + wn * 64 + nt * 8 + cq;
            float b0v = bias[col], b1v = bias[col + 1];
            int hh = col / 192, ff = col - hh * 192;
            int sel = ff >> 6, ffl = ff & 63;
            fp16* ph = (sel == 0) ? g_k16 : (sel == 1) ? g_q16 : g_v16;
            float scale = (sel == 1) ? 0.125f : 1.0f;
#pragma unroll
            for (int rh = 0; rh < 2; rh++) {
                int m = m0 + wm * 32 + t * 16 + g + rh * 8;
                int bb = m >> 11, n = m & (N_ - 1);
                uint32_t hp = pack_f16((acc[t][nt][rh * 2] + b0v) * scale,
                                       (acc[t][nt][rh * 2 + 1] + b1v) * scale);
                size_t idx = ((size_t)(bb * H_ + hh) * N_ + n) * HD_ + ffl;
                *(uint32_t*)(ph + idx) = hp;
            }
        }
}

// ---------------- kernel 2: causal flash attention (fp16 HMMA, fp16x2 exp2) ---
// KV buffer: K@0 (64 x pitch144 = 9216), V@9216. ABUF=18432, double buffered.
// Q @36864 (128 x 144 = 18432). Total 55296.
#define ABUF16 18432
#define ATTN_SMEM (2*ABUF16 + 18432)
__global__ __launch_bounds__(256, 2) void attn_mma()
{
    extern __shared__ __align__(16) uint8_t dsm[];
    const uint32_t sb = smem_u32(dsm);
    const int tid = threadIdx.x, lane = tid & 31, w = tid >> 5;
    const int qt = (int)gridDim.x - 1 - (int)blockIdx.x;   // big tiles first
    const int bhd = blockIdx.y;
    const int g = lane >> 2, cq = (lane & 3) * 2;
    const int lrA = (lane & 7) + ((lane >> 3) & 1) * 8, lcA = ((lane >> 4) & 1) * 8;
    const int lrB = (lane & 7) + ((lane >> 4) & 1) * 8, lcB = ((lane >> 3) & 1) * 8;
    const uint32_t QB = sb + 2 * ABUF16;
    const float L2E = 1.4426950408889634f;

    const fp16* srcKV[4]; uint32_t dstKV[4];
#pragma unroll
    for (int t = 0; t < 4; t++) {
        int j = (t & 1) * 256 + tid, row = j >> 3, sg = (j & 7) * 8;
        srcKV[t] = ((t < 2) ? g_k16 : g_v16) + (size_t)(bhd * N_ + row) * HD_ + sg;
        dstKV[t] = ((t < 2) ? 0u : 9216u) + row * 144 + sg * 2;
    }
#pragma unroll
    for (int t = 0; t < 4; t++) CP16(sb + dstKV[t], srcKV[t]);
    CP_COMMIT();

    // stage Q (128x64 fp16, pre-scaled) in smem; frags loaded on demand
#pragma unroll
    for (int t = 0; t < 4; t++) {
        int j = t * 256 + tid, row = j >> 3, sg = (j & 7) * 8;
        uint4 v = ((const uint4*)g_q16)[((size_t)(bhd * N_ + qt * 128 + row) * HD_ + sg) >> 3];
        *(uint4*)((size_t)dsm + (QB - sb) + row * 144 + sg * 2) = v;
    }

    float o[8][4];
#pragma unroll
    for (int nt = 0; nt < 8; nt++)
#pragma unroll
        for (int j = 0; j < 4; j++) o[nt][j] = 0.f;
    float mrow[2] = {-1e30f, -1e30f}, lrow[2] = {0.f, 0.f};
    const int qr0 = qt * 128 + w * 16 + g;
    const int wmaxk = qt * 128 + w * 16 + 15;
    const int ktmax = 2 * qt + 1;

    for (int kt = 0; kt <= ktmax; kt++) {
        const uint32_t base = sb + (uint32_t)(kt & 1) * ABUF16;
        CP_WAIT0();
        __syncthreads();
        if (kt < ktmax) {
            const uint32_t nb = sb + (uint32_t)((kt + 1) & 1) * ABUF16;
#pragma unroll
            for (int t = 0; t < 4; t++) { srcKV[t] += 64 * HD_; CP16(nb + dstKV[t], srcKV[t]); }
            CP_COMMIT();
        }
        if (kt * 64 <= wmaxk) {
            const uint32_t KB = base, VB = base + 9216;
            float s_[8][4];
#pragma unroll
            for (int nt = 0; nt < 8; nt++)
#pragma unroll
                for (int j = 0; j < 4; j++) s_[nt][j] = 0.f;
#pragma unroll
            for (int kk = 0; kk < 4; kk++) {
                uint32_t qf[4];
                ldm4(qf, QB + (w * 16 + lrA) * 144 + (kk * 16 + lcA) * 2);
#pragma unroll
                for (int np = 0; np < 4; np++) {
                    uint32_t kf[4];
                    ldm4(kf, KB + (np * 16 + lrB) * 144 + (kk * 16 + lcB) * 2);
#pragma unroll
                    for (int j = 0; j < 2; j++)
                        mma_f16(s_[np * 2 + j], qf, kf[j * 2], kf[j * 2 + 1]);
                }
            }
            // causal mask (Q already scaled)
            const int kbase = kt * 64;
#pragma unroll
            for (int nt = 0; nt < 8; nt++)
#pragma unroll
                for (int j = 0; j < 4; j++) {
                    int colg = kbase + nt * 8 + cq + (j & 1);
                    int rowg = (j < 2) ? qr0 : qr0 + 8;
                    if (colg > rowg) s_[nt][j] = -1e30f;
                }
            // online softmax; P computed as fp16x2 via ex2.approx.f16x2, stored
            // back into s_ slots [0]/[2] as packed half2 (rows g / g+8).
#pragma unroll
            for (int a = 0; a < 2; a++) {
                float tm = -1e30f;
#pragma unroll
                for (int nt = 0; nt < 8; nt++)
                    tm = fmaxf(tm, fmaxf(s_[nt][a * 2], s_[nt][a * 2 + 1]));
                tm = fmaxf(tm, __shfl_xor_sync(0xffffffffu, tm, 1));
                tm = fmaxf(tm, __shfl_xor_sync(0xffffffffu, tm, 2));
                float mn = fmaxf(mrow[a], tm);
                float alpha = __expf(mrow[a] - mn);
                float mnl = mn * L2E;
                float rs = 0.f;
#pragma unroll
                for (int nt = 0; nt < 8; nt++) {
                    float e0 = __fmaf_rn(s_[nt][a * 2],     L2E, -mnl);
                    float e1 = __fmaf_rn(s_[nt][a * 2 + 1], L2E, -mnl);
                    __half2 h = h2exp2(__floats2half2_rn(e0, e1));
                    float2 pf = __half22float2(h);
                    rs += pf.x + pf.y;
                    s_[nt][a * 2] = __uint_as_float(*reinterpret_cast<uint32_t*>(&h));
                }
                rs += __shfl_xor_sync(0xffffffffu, rs, 1);
                rs += __shfl_xor_sync(0xffffffffu, rs, 2);
                lrow[a] = lrow[a] * alpha + rs;
                mrow[a] = mn;
#pragma unroll
                for (int nt = 0; nt < 8; nt++) {
                    o[nt][a * 2]     *= alpha;
                    o[nt][a * 2 + 1] *= alpha;
                }
            }
            // O += P V; P a-frags are the packed half2 bits already in s_
#pragma unroll
            for (int kk = 0; kk < 4; kk++) {
                uint32_t pa[4];
                pa[0] = __float_as_uint(s_[2 * kk][0]);
                pa[1] = __float_as_uint(s_[2 * kk][2]);
                pa[2] = __float_as_uint(s_[2 * kk + 1][0]);
                pa[3] = __float_as_uint(s_[2 * kk + 1][2]);
#pragma unroll
                for (int np = 0; np < 4; np++) {
                    uint32_t vf[4];
                    ldm4t(vf, VB + (kk * 16 + lrA) * 144 + (np * 16 + lcA) * 2);
#pragma unroll
                    for (int j = 0; j < 2; j++)
                        mma_f16(o[np * 2 + j], pa, vf[j * 2], vf[j * 2 + 1]);
                }
            }
        }
    }

    // epilogue: O/l -> fp16 sa [B,N,E]
    const int bb = bhd >> 4, hh = bhd & 15;
    float inv[2] = {1.f / lrow[0], 1.f / lrow[1]};
#pragma unroll
    for (int nt = 0; nt < 8; nt++) {
        int d = hh * 64 + nt * 8 + cq;
#pragma unroll
        for (int a = 0; a < 2; a++) {
            int n = qt * 128 + w * 16 + g + a * 8;
            uint32_t hp = pack_f16(o[nt][a * 2] * inv[a], o[nt][a * 2 + 1] * inv[a]);
            *(uint32_t*)(g_sa16 + (size_t)(bb * N_ + n) * E_ + d) = hp;
        }
    }
}

// ---------------- kernel 3: output projection (fp16 HMMA, BK=64) --------------
__global__ __launch_bounds__(256, 2) void out_mma(const float* __restrict__ bias,
                                                  float* __restrict__ out)
{
    extern __shared__ __align__(16) uint8_t dsm[];
    const uint32_t sb = smem_u32(dsm);
    const int tid = threadIdx.x, lane = tid & 31, wid = tid >> 5;
    const int wm = wid >> 1, wn = wid & 1;
    const int m0 = blockIdx.y * 128, n0 = blockIdx.x * 128;
    const int g = lane >> 2, cq = (lane & 3) * 2;
    const int lrA = (lane & 7) + ((lane >> 3) & 1) * 8, lcA = ((lane >> 4) & 1) * 8;

    const fp16* srcA[4]; uint32_t dstA[4];
    const fp16* srcB[4]; uint32_t dstB[4];
#pragma unroll
    for (int t = 0; t < 4; t++) {
        int j = t * 256 + tid, row = j >> 3, sg = (j & 7) * 8;
        srcA[t] = g_sa16 + (size_t)(m0 + row) * E_ + sg;
        dstA[t] = row * 144 + sg * 2;
    }
#pragma unroll
    for (int t = 0; t < 4; t++) {
        int j = t * 256 + tid, k = j >> 4, sg = (j & 15) * 8;
        srcB[t] = g_wo16 + (size_t)k * E_ + n0 + sg;
        dstB[t] = 18432u + k * 272 + sg * 2;
    }

    float acc[2][8][4];
#pragma unroll
    for (int t = 0; t < 2; t++)
#pragma unroll
        for (int nt = 0; nt < 8; nt++)
#pragma unroll
            for (int j = 0; j < 4; j++) acc[t][nt][j] = 0.f;

#pragma unroll
    for (int t = 0; t < 4; t++) CP16(sb + dstA[t], srcA[t]);
#pragma unroll
    for (int t = 0; t < 4; t++) CP16(sb + dstB[t], srcB[t]);
    CP_COMMIT();

    for (int kc = 0; kc < 16; kc++) {
        const uint32_t base = sb + (uint32_t)(kc & 1) * GBUF2;
        CP_WAIT0();
        __syncthreads();
        if (kc < 15) {
            const uint32_t nb = sb + (uint32_t)((kc + 1) & 1) * GBUF2;
#pragma unroll
            for (int t = 0; t < 4; t++) { srcA[t] += 64;      CP16(nb + dstA[t], srcA[t]); }
#pragma unroll
            for (int t = 0; t < 4; t++) { srcB[t] += 64 * E_; CP16(nb + dstB[t], srcB[t]); }
            CP_COMMIT();
        }
#pragma unroll
        for (int kk = 0; kk < 4; kk++) {
            uint32_t af[2][4];
#pragma unroll
            for (int t = 0; t < 2; t++)
                ldm4(af[t], base + (wm * 32 + t * 16 + lrA) * 144 + (kk * 16 + lcA) * 2);
#pragma unroll
            for (int np = 0; np < 4; np++) {
                uint32_t bf[4];
                ldm4t(bf, base + 18432u + (kk * 16 + lrA) * 272
                           + (wn * 64 + np * 16 + lcA) * 2);
#pragma unroll
                for (int t = 0; t < 2; t++)
#pragma unroll
                    for (int j = 0; j < 2; j++)
                        mma_f16(acc[t][np * 2 + j], af[t], bf[j * 2], bf[j * 2 + 1]);
            }
        }
    }

#pragma unroll
    for (int t = 0; t < 2; t++)
#pragma unroll
        for (int nt = 0; nt < 8; nt++) {
            int col = n0 + wn * 64 + nt * 8 + cq;
            float b0v = bias[col], b1v = bias[col + 1];
#pragma unroll
            for (int rh = 0; rh < 2; rh++) {
                int m = m0 + wm * 32 + t * 16 + g + rh * 8;
                float2 v;
                v.x = acc[t][nt][rh * 2 + 0] + b0v;
                v.y = acc[t][nt][rh * 2 + 1] + b1v;
                *(float2*)(out + (size_t)m * E_ + col) = v;
            }
        }
}

// ---------------------------------------------------------------------------
extern "C" void kernel_launch(void* const* d_in, const int* in_sizes, int n_in,
                              void* d_out, int out_size)
{
    const float* x    = (const float*)d_in[0];   // [B,N,E]
    const float* Wqkv = (const float*)d_in[1];   // [H,E,192]
    const float* bqkv = (const float*)d_in[2];   // [H,192]
    const float* Wout = (const float*)d_in[3];   // [E,E]
    const float* bout = (const float*)d_in[4];   // [E]
    float* out = (float*)d_out;                  // [B,N,E]

    static int configured = 0;
    if (!configured) {
        cudaFuncSetAttribute(qkv_mma,  cudaFuncAttributeMaxDynamicSharedMemorySize, GEMM_SMEM);
        cudaFuncSetAttribute(out_mma,  cudaFuncAttributeMaxDynamicSharedMemorySize, GEMM_SMEM);
        cudaFuncSetAttribute(attn_mma, cudaFuncAttributeMaxDynamicSharedMemorySize, ATTN_SMEM);
        configured = 1;
    }

    cvt_all<<<2048, 256>>>(x, Wqkv, Wout);

    dim3 g1(QKVC / 128, M_ / 128);   // 24 x 32
    qkv_mma<<<g1, 256, GEMM_SMEM>>>(bqkv);

    dim3 g2(N_ / 128, B_ * H_);      // 16 x 32
    attn_mma<<<g2, 256, ATTN_SMEM>>>();

    dim3 g3(E_ / 128, M_ / 128);     // 8 x 32
    out_mma<<<g3, 256, GEMM_SMEM>>>(bout, out);
}